// round 1
// baseline (speedup 1.0000x reference)
#include <cuda_runtime.h>
#include <cstdint>

#define NN 50000
#define F  256

// Scratch (no cudaMalloc allowed): Chebyshev intermediates + CSR row pointers.
__device__ float g_T1[(size_t)NN * F];
__device__ float g_T2[(size_t)NN * F];
__device__ int   g_rp[NN + 1];

// ---------------------------------------------------------------------------
// row_ptr: lower_bound of each node id in the sorted edge_row array.
// ---------------------------------------------------------------------------
__global__ void build_rowptr_kernel(const int* __restrict__ erow, int E, int N) {
    int i = blockIdx.x * blockDim.x + threadIdx.x;
    if (i > N) return;
    int lo = 0, hi = E;
    while (lo < hi) {
        int mid = (lo + hi) >> 1;
        if (erow[mid] < i) lo = mid + 1; else hi = mid;
    }
    g_rp[i] = lo;
}

// ---------------------------------------------------------------------------
// SpMM: one block (256 threads) per node row; thread t owns feature t.
// MODE 0:  g_T1 = L @ x
// MODE 1:  g_T2 = 2 * (L @ g_T1) - x
// Edge (col, w) lists staged in smem; gathers unrolled x8 for L2 MLP.
// ---------------------------------------------------------------------------
template <int MODE>
__global__ void spmm_kernel(const float* __restrict__ x,
                            const int*   __restrict__ ecol,
                            const float* __restrict__ ew) {
    __shared__ int   scol[256];
    __shared__ float swt[256];

    const float* __restrict__ src = (MODE == 0) ? x : g_T1;
    float* __restrict__ dst       = (MODE == 0) ? g_T1 : g_T2;

    int node = blockIdx.x;
    int tid  = threadIdx.x;
    int r0 = g_rp[node];
    int r1 = g_rp[node + 1];

    float acc = 0.f;
    for (int base = r0; base < r1; base += 256) {
        int cnt = min(256, r1 - base);
        __syncthreads();
        if (tid < cnt) {
            scol[tid] = ecol[base + tid];
            swt[tid]  = ew[base + tid];
        }
        __syncthreads();
        int j = 0;
        for (; j + 8 <= cnt; j += 8) {
            float v[8], w[8];
            #pragma unroll
            for (int u = 0; u < 8; ++u) {
                w[u] = swt[j + u];
                v[u] = __ldg(src + (size_t)scol[j + u] * F + tid);
            }
            #pragma unroll
            for (int u = 0; u < 8; ++u) acc = fmaf(w[u], v[u], acc);
        }
        for (; j < cnt; ++j)
            acc = fmaf(swt[j], __ldg(src + (size_t)scol[j] * F + tid), acc);
    }

    size_t idx = (size_t)node * F + tid;
    if (MODE == 0) dst[idx] = acc;
    else           dst[idx] = 2.0f * acc - x[idx];
}

// ---------------------------------------------------------------------------
// GEMM: out[50000,256] = [x | T1 | T2] (50000 x 768) @ W(768 x 256) + bias
// tf32 mma.sync m16n8k8, inputs rounded with cvt.rna (zero-mean error).
// Block: 256 thr (8 warps, 4Mx2N), tile BM=128 BN=64 BK=32.
// ---------------------------------------------------------------------------
__device__ __forceinline__ uint32_t f2tf32(float x) {
    uint32_t r;
    asm("cvt.rna.tf32.f32 %0, %1;" : "=r"(r) : "f"(x));
    return r;
}

#define BM 128
#define BN 64
#define BK 32
#define AP 36   // A smem pitch: (36*row + col) % 32 = (4*row + col) -> conflict-free frags
#define BP 72   // B smem pitch: (72*k + n) % 32 = (8*k + n)        -> conflict-free frags

__global__ __launch_bounds__(256)
void cheb_gemm_kernel(const float* __restrict__ x,
                      const float* __restrict__ w,     // [768][256] flattened (K,F_IN,F_OUT)
                      const float* __restrict__ bias,
                      float* __restrict__ out,
                      int N) {
    __shared__ float As[BM][AP];
    __shared__ float Bs[BK][BP];

    int tid  = threadIdx.x;
    int warp = tid >> 5, lane = tid & 31;
    int g = lane >> 2, t = lane & 3;   // mma group / thread-in-group
    int wm = (warp >> 1) * 32;         // 4 warps along M
    int wn = (warp & 1) * 32;          // 2 warps along N
    int row0 = blockIdx.x * BM;
    int col0 = blockIdx.y * BN;

    float acc[2][4][4];
    #pragma unroll
    for (int mi = 0; mi < 2; ++mi)
        #pragma unroll
        for (int ni = 0; ni < 4; ++ni)
            #pragma unroll
            for (int q = 0; q < 4; ++q) acc[mi][ni][q] = 0.f;

    for (int kb = 0; kb < 3 * F; kb += BK) {
        const float* Asrc = (kb < 256) ? x : (kb < 512) ? g_T1 : g_T2;
        int colA = kb & 255;

        // ---- stage A: 128 rows x 32 k  (idx: kq = idx&7, m = idx>>3) ----
        #pragma unroll
        for (int it = 0; it < 4; ++it) {
            int idx = tid + it * 256;
            int kq = idx & 7, m = idx >> 3;
            int grow = row0 + m;
            float4 v = make_float4(0.f, 0.f, 0.f, 0.f);
            if (grow < N)
                v = *reinterpret_cast<const float4*>(Asrc + (size_t)grow * 256 + colA + kq * 4);
            float4 c;
            c.x = __uint_as_float(f2tf32(v.x));
            c.y = __uint_as_float(f2tf32(v.y));
            c.z = __uint_as_float(f2tf32(v.z));
            c.w = __uint_as_float(f2tf32(v.w));
            *reinterpret_cast<float4*>(&As[m][kq * 4]) = c;
        }
        // ---- stage B: 32 k x 64 n  (idx: n4 = idx&15, k = idx>>4) ----
        #pragma unroll
        for (int it = 0; it < 2; ++it) {
            int idx = tid + it * 256;
            int n4 = idx & 15, k = idx >> 4;
            float4 v = *reinterpret_cast<const float4*>(w + (size_t)(kb + k) * 256 + col0 + n4 * 4);
            float4 c;
            c.x = __uint_as_float(f2tf32(v.x));
            c.y = __uint_as_float(f2tf32(v.y));
            c.z = __uint_as_float(f2tf32(v.z));
            c.w = __uint_as_float(f2tf32(v.w));
            *reinterpret_cast<float4*>(&Bs[k][n4 * 4]) = c;
        }
        __syncthreads();

        #pragma unroll
        for (int ks = 0; ks < 4; ++ks) {
            int k0 = ks * 8;
            uint32_t a[2][4], b[4][2];
            #pragma unroll
            for (int mi = 0; mi < 2; ++mi) {
                int mrow = wm + mi * 16 + g;
                a[mi][0] = __float_as_uint(As[mrow][k0 + t]);
                a[mi][1] = __float_as_uint(As[mrow + 8][k0 + t]);
                a[mi][2] = __float_as_uint(As[mrow][k0 + t + 4]);
                a[mi][3] = __float_as_uint(As[mrow + 8][k0 + t + 4]);
            }
            #pragma unroll
            for (int ni = 0; ni < 4; ++ni) {
                int ncol = wn + ni * 8 + g;
                b[ni][0] = __float_as_uint(Bs[k0 + t][ncol]);
                b[ni][1] = __float_as_uint(Bs[k0 + t + 4][ncol]);
            }
            #pragma unroll
            for (int mi = 0; mi < 2; ++mi)
                #pragma unroll
                for (int ni = 0; ni < 4; ++ni)
                    asm volatile(
                        "mma.sync.aligned.m16n8k8.row.col.f32.tf32.tf32.f32 "
                        "{%0,%1,%2,%3}, {%4,%5,%6,%7}, {%8,%9}, {%0,%1,%2,%3};"
                        : "+f"(acc[mi][ni][0]), "+f"(acc[mi][ni][1]),
                          "+f"(acc[mi][ni][2]), "+f"(acc[mi][ni][3])
                        : "r"(a[mi][0]), "r"(a[mi][1]), "r"(a[mi][2]), "r"(a[mi][3]),
                          "r"(b[ni][0]), "r"(b[ni][1]));
        }
        __syncthreads();
    }

    // ---- epilogue: + bias, guarded stores ----
    #pragma unroll
    for (int ni = 0; ni < 4; ++ni) {
        int col = col0 + wn + ni * 8 + 2 * t;
        float b0 = bias[col], b1 = bias[col + 1];
        #pragma unroll
        for (int mi = 0; mi < 2; ++mi) {
            int row = row0 + wm + mi * 16 + g;
            if (row < N) {
                float2 v = make_float2(acc[mi][ni][0] + b0, acc[mi][ni][1] + b1);
                *reinterpret_cast<float2*>(out + (size_t)row * 256 + col) = v;
            }
            if (row + 8 < N) {
                float2 v = make_float2(acc[mi][ni][2] + b0, acc[mi][ni][3] + b1);
                *reinterpret_cast<float2*>(out + (size_t)(row + 8) * 256 + col) = v;
            }
        }
    }
}

// ---------------------------------------------------------------------------
extern "C" void kernel_launch(void* const* d_in, const int* in_sizes, int n_in,
                              void* d_out, int out_size) {
    const float* x    = (const float*)d_in[0];   // [N, 256]
    const int*   erow = (const int*)  d_in[1];   // [E] sorted
    const int*   ecol = (const int*)  d_in[2];   // [E]
    const float* ew   = (const float*)d_in[3];   // [E]
    const float* wgt  = (const float*)d_in[4];   // [3, 256, 256]
    const float* bias = (const float*)d_in[5];   // [256]
    float* out = (float*)d_out;

    int N = in_sizes[0] / F;   // 50000
    int E = in_sizes[1];       // 1600000

    build_rowptr_kernel<<<(N + 1 + 255) / 256, 256>>>(erow, E, N);
    spmm_kernel<0><<<N, 256>>>(x, ecol, ew);   // T1 = L x
    spmm_kernel<1><<<N, 256>>>(x, ecol, ew);   // T2 = 2 L T1 - x

    dim3 grid((N + BM - 1) / BM, F / BN);      // (391, 4)
    cheb_gemm_kernel<<<grid, 256>>>(x, wgt, bias, out, N);
}

// round 2
// speedup vs baseline: 2.3173x; 2.3173x over previous
#include <cuda_runtime.h>
#include <cuda_fp16.h>
#include <cstdint>

#define NN 50000
#define F  256
#define KW 3

// Scratch (no cudaMalloc allowed).
__device__ __half g_xh[(size_t)NN * F];
__device__ __half g_T1[(size_t)NN * F];
__device__ __half g_T2[(size_t)NN * F];
__device__ __half g_wh[(size_t)KW * F * F];
__device__ int    g_rp[NN + 1];

// ---------------------------------------------------------------------------
// row_ptr: lower_bound of each node id in the sorted edge_row array.
// ---------------------------------------------------------------------------
__global__ void build_rowptr_kernel(const int* __restrict__ erow, int E, int N) {
    int i = blockIdx.x * blockDim.x + threadIdx.x;
    if (i > N) return;
    int lo = 0, hi = E;
    while (lo < hi) {
        int mid = (lo + hi) >> 1;
        if (erow[mid] < i) lo = mid + 1; else hi = mid;
    }
    g_rp[i] = lo;
}

// ---------------------------------------------------------------------------
// fp32 -> fp16 converters (RN rounding, unbiased)
// ---------------------------------------------------------------------------
__global__ void cvt_kernel(const float* __restrict__ src, __half* __restrict__ dst, int n4) {
    int i = blockIdx.x * blockDim.x + threadIdx.x;
    if (i >= n4) return;
    float4 v = *reinterpret_cast<const float4*>(src + (size_t)i * 4);
    __half2 h0 = __floats2half2_rn(v.x, v.y);
    __half2 h1 = __floats2half2_rn(v.z, v.w);
    uint2 o;
    o.x = *reinterpret_cast<uint32_t*>(&h0);
    o.y = *reinterpret_cast<uint32_t*>(&h1);
    *reinterpret_cast<uint2*>(dst + (size_t)i * 4) = o;
}

// ---------------------------------------------------------------------------
// SpMM: warp per node row. Lane l owns features [8l, 8l+8) as one uint4
// (8 fp16). Edges broadcast via shfl; gathers batched x4 for L2 MLP.
// MODE 0: g_T1 = L @ g_xh        MODE 1: g_T2 = 2*(L @ g_T1) - g_xh
// ---------------------------------------------------------------------------
__device__ __forceinline__ void accum8(float acc[8], uint4 v, float w) {
    const __half2* h = reinterpret_cast<const __half2*>(&v);
    #pragma unroll
    for (int q = 0; q < 4; ++q) {
        float2 f = __half22float2(h[q]);
        acc[2 * q]     = fmaf(w, f.x, acc[2 * q]);
        acc[2 * q + 1] = fmaf(w, f.y, acc[2 * q + 1]);
    }
}

template <int MODE>
__global__ __launch_bounds__(256)
void spmm_h_kernel(const int* __restrict__ ecol, const float* __restrict__ ew) {
    int warp = threadIdx.x >> 5, lane = threadIdx.x & 31;
    int node = blockIdx.x * 8 + warp;
    if (node >= NN) return;

    const uint4* __restrict__ src =
        reinterpret_cast<const uint4*>((MODE == 0) ? g_xh : g_T1);
    __half* dst = (MODE == 0) ? g_T1 : g_T2;

    int r0 = g_rp[node], r1 = g_rp[node + 1];
    float acc[8];
    #pragma unroll
    for (int q = 0; q < 8; ++q) acc[q] = 0.f;

    for (int base = r0; base < r1; base += 32) {
        int cnt = min(32, r1 - base);
        int   c  = 0;
        float wv = 0.f;
        if (base + lane < r1) {
            c  = ecol[base + lane];
            wv = ew[base + lane];
        }
        int j = 0;
        for (; j + 4 <= cnt; j += 4) {
            int   c0 = __shfl_sync(0xffffffffu, c,  j);
            int   c1 = __shfl_sync(0xffffffffu, c,  j + 1);
            int   c2 = __shfl_sync(0xffffffffu, c,  j + 2);
            int   c3 = __shfl_sync(0xffffffffu, c,  j + 3);
            float w0 = __shfl_sync(0xffffffffu, wv, j);
            float w1 = __shfl_sync(0xffffffffu, wv, j + 1);
            float w2 = __shfl_sync(0xffffffffu, wv, j + 2);
            float w3 = __shfl_sync(0xffffffffu, wv, j + 3);
            uint4 v0 = __ldg(&src[(size_t)c0 * 32 + lane]);
            uint4 v1 = __ldg(&src[(size_t)c1 * 32 + lane]);
            uint4 v2 = __ldg(&src[(size_t)c2 * 32 + lane]);
            uint4 v3 = __ldg(&src[(size_t)c3 * 32 + lane]);
            accum8(acc, v0, w0);
            accum8(acc, v1, w1);
            accum8(acc, v2, w2);
            accum8(acc, v3, w3);
        }
        for (; j < cnt; ++j) {
            int   cj = __shfl_sync(0xffffffffu, c,  j);
            float wj = __shfl_sync(0xffffffffu, wv, j);
            uint4 v = __ldg(&src[(size_t)cj * 32 + lane]);
            accum8(acc, v, wj);
        }
    }

    if (MODE == 1) {
        uint4 xv = reinterpret_cast<const uint4*>(g_xh)[(size_t)node * 32 + lane];
        const __half2* h = reinterpret_cast<const __half2*>(&xv);
        #pragma unroll
        for (int q = 0; q < 4; ++q) {
            float2 f = __half22float2(h[q]);
            acc[2 * q]     = 2.f * acc[2 * q]     - f.x;
            acc[2 * q + 1] = 2.f * acc[2 * q + 1] - f.y;
        }
    }

    __half2 o[4];
    #pragma unroll
    for (int q = 0; q < 4; ++q) o[q] = __floats2half2_rn(acc[2 * q], acc[2 * q + 1]);
    reinterpret_cast<uint4*>(dst)[(size_t)node * 32 + lane] =
        *reinterpret_cast<uint4*>(o);
}

// ---------------------------------------------------------------------------
// GEMM: out[N,256] = [xh | T1 | T2](N x 768) @ Wh(768 x 256) + bias
// fp16 mma m16n8k16 (fp32 accum), cp.async double-buffered, BM=BN=128 BK=32.
// 8 warps as 4M x 2N; warp tile 32x64. ldmatrix with conflict-free pitches.
// ---------------------------------------------------------------------------
#define GBM 128
#define GBN 128
#define GBK 32
#define PA  40    // A smem pitch (halves): 80B rows -> 8-row phase hits all 32 banks
#define PB  136   // B smem pitch (halves): 272B rows -> same property

__device__ __forceinline__ void cp16(uint32_t dst, const void* src, int sz) {
    asm volatile("cp.async.cg.shared.global [%0], [%1], 16, %2;\n"
                 :: "r"(dst), "l"(src), "r"(sz));
}
__device__ __forceinline__ void ldsm_x4(uint32_t r[4], uint32_t addr) {
    asm volatile("ldmatrix.sync.aligned.m8n8.x4.shared.b16 {%0,%1,%2,%3}, [%4];"
                 : "=r"(r[0]), "=r"(r[1]), "=r"(r[2]), "=r"(r[3]) : "r"(addr));
}
__device__ __forceinline__ void ldsm_x4_t(uint32_t r[4], uint32_t addr) {
    asm volatile("ldmatrix.sync.aligned.m8n8.x4.trans.shared.b16 {%0,%1,%2,%3}, [%4];"
                 : "=r"(r[0]), "=r"(r[1]), "=r"(r[2]), "=r"(r[3]) : "r"(addr));
}

__global__ __launch_bounds__(256, 2)
void gemm_h_kernel(const float* __restrict__ bias, float* __restrict__ out, int N) {
    __shared__ __half sA[2][GBM * PA];
    __shared__ __half sB[2][GBK * PB];

    int tid  = threadIdx.x;
    int warp = tid >> 5, lane = tid & 31;
    int row0 = blockIdx.x * GBM, col0 = blockIdx.y * GBN;
    int wm = (warp >> 1) * 32;       // 4 warps along M
    int wn = (warp & 1) * 64;        // 2 warps along N

    float acc[2][8][4];
    #pragma unroll
    for (int mi = 0; mi < 2; ++mi)
        #pragma unroll
        for (int ni = 0; ni < 8; ++ni)
            #pragma unroll
            for (int q = 0; q < 4; ++q) acc[mi][ni][q] = 0.f;

    uint32_t aBase = (uint32_t)__cvta_generic_to_shared(&sA[0][0]);
    uint32_t bBase = (uint32_t)__cvta_generic_to_shared(&sB[0][0]);
    const uint32_t aStage = GBM * PA * 2;  // bytes
    const uint32_t bStage = GBK * PB * 2;

    auto issue = [&](int s, int iter) {
        const __half* asrc = (iter < 8) ? g_xh : (iter < 16) ? g_T1 : g_T2;
        int colA = (iter * GBK) & 255;
        #pragma unroll
        for (int it = 0; it < 2; ++it) {
            int idx = tid + it * 256;
            int r = idx >> 2, c = idx & 3;
            int grow = row0 + r;
            const __half* g = asrc + (size_t)min(grow, NN - 1) * 256 + colA + c * 8;
            cp16(aBase + s * aStage + (uint32_t)(r * PA + c * 8) * 2, g,
                 grow < N ? 16 : 0);
        }
        int kb = iter * GBK;
        #pragma unroll
        for (int it = 0; it < 2; ++it) {
            int idx = tid + it * 256;
            int k = idx >> 4, c = idx & 15;
            const __half* g = g_wh + (size_t)(kb + k) * 256 + col0 + c * 8;
            cp16(bBase + s * bStage + (uint32_t)(k * PB + c * 8) * 2, g, 16);
        }
    };

    issue(0, 0);
    asm volatile("cp.async.commit_group;");

    for (int iter = 0; iter < 24; ++iter) {
        int s = iter & 1;
        if (iter + 1 < 24) {
            issue(s ^ 1, iter + 1);
            asm volatile("cp.async.commit_group;");
            asm volatile("cp.async.wait_group 1;");
        } else {
            asm volatile("cp.async.wait_group 0;");
        }
        __syncthreads();

        uint32_t aS = aBase + s * aStage;
        uint32_t bS = bBase + s * bStage;
        #pragma unroll
        for (int kc = 0; kc < 2; ++kc) {
            uint32_t a[2][4], b[4][4];
            #pragma unroll
            for (int mi = 0; mi < 2; ++mi) {
                int r = wm + mi * 16 + (lane & 15);
                ldsm_x4(a[mi], aS + (uint32_t)(r * PA + kc * 16 + (lane >> 4) * 8) * 2);
            }
            #pragma unroll
            for (int bi = 0; bi < 4; ++bi) {
                int k = kc * 16 + (lane & 15);
                ldsm_x4_t(b[bi], bS + (uint32_t)(k * PB + wn + bi * 16 + (lane >> 4) * 8) * 2);
            }
            #pragma unroll
            for (int mi = 0; mi < 2; ++mi)
                #pragma unroll
                for (int ni = 0; ni < 8; ++ni) {
                    uint32_t b0 = b[ni >> 1][(ni & 1) * 2];
                    uint32_t b1 = b[ni >> 1][(ni & 1) * 2 + 1];
                    asm volatile(
                        "mma.sync.aligned.m16n8k16.row.col.f32.f16.f16.f32 "
                        "{%0,%1,%2,%3}, {%4,%5,%6,%7}, {%8,%9}, {%0,%1,%2,%3};"
                        : "+f"(acc[mi][ni][0]), "+f"(acc[mi][ni][1]),
                          "+f"(acc[mi][ni][2]), "+f"(acc[mi][ni][3])
                        : "r"(a[mi][0]), "r"(a[mi][1]), "r"(a[mi][2]), "r"(a[mi][3]),
                          "r"(b0), "r"(b1));
                }
        }
        __syncthreads();
    }

    // Epilogue: + bias, fp32 stores.
    int g = lane >> 2, t = lane & 3;
    #pragma unroll
    for (int ni = 0; ni < 8; ++ni) {
        int col = col0 + wn + ni * 8 + t * 2;
        float b0 = __ldg(bias + col), b1 = __ldg(bias + col + 1);
        #pragma unroll
        for (int mi = 0; mi < 2; ++mi) {
            int row = row0 + wm + mi * 16 + g;
            if (row < N) {
                float2 v = make_float2(acc[mi][ni][0] + b0, acc[mi][ni][1] + b1);
                *reinterpret_cast<float2*>(out + (size_t)row * 256 + col) = v;
            }
            if (row + 8 < N) {
                float2 v = make_float2(acc[mi][ni][2] + b0, acc[mi][ni][3] + b1);
                *reinterpret_cast<float2*>(out + (size_t)(row + 8) * 256 + col) = v;
            }
        }
    }
}

// ---------------------------------------------------------------------------
extern "C" void kernel_launch(void* const* d_in, const int* in_sizes, int n_in,
                              void* d_out, int out_size) {
    const float* x    = (const float*)d_in[0];   // [N, 256]
    const int*   erow = (const int*)  d_in[1];   // [E] sorted
    const int*   ecol = (const int*)  d_in[2];   // [E]
    const float* ew   = (const float*)d_in[3];   // [E]
    const float* wgt  = (const float*)d_in[4];   // [3, 256, 256]
    const float* bias = (const float*)d_in[5];   // [256]
    float* out = (float*)d_out;

    int N = in_sizes[0] / F;   // 50000
    int E = in_sizes[1];       // 1600000

    build_rowptr_kernel<<<(N + 1 + 255) / 256, 256>>>(erow, E, N);

    __half* xh_p; cudaGetSymbolAddress((void**)&xh_p, g_xh);
    __half* wh_p; cudaGetSymbolAddress((void**)&wh_p, g_wh);
    cvt_kernel<<<(N * F / 4 + 255) / 256, 256>>>(x, xh_p, N * F / 4);
    cvt_kernel<<<(KW * F * F / 4 + 255) / 256, 256>>>(wgt, wh_p, KW * F * F / 4);

    spmm_h_kernel<0><<<(N + 7) / 8, 256>>>(ecol, ew);   // T1 = L xh
    spmm_h_kernel<1><<<(N + 7) / 8, 256>>>(ecol, ew);   // T2 = 2 L T1 - xh

    dim3 grid((N + GBM - 1) / GBM, F / GBN);            // (391, 2)
    gemm_h_kernel<<<grid, 256>>>(bias, out, N);
}